// round 11
// baseline (speedup 1.0000x reference)
#include <cuda_runtime.h>
#include <cstdint>

#define D_DIM 768
#define OUT_DIM 196
#define NPAD 208
#define TM 128
#define BK 32
#define NTILES 24
#define NTHREADS 512
#define NFRAG 13

#define XROWW 36                      // x row stride (words)
#define XW (TM * XROWW)               // 4608 words / stage
#define WROWW 40                      // W row stride (words) = 20 float2
#define WW (NPAD * WROWW)             // 8320 words / stage
#define XSTAGES 5
#define WSTAGES 4

#define X_OFF 0
#define W_OFF (XSTAGES * XW)                       // 23040
#define MEAN_OFF (W_OFF + WSTAGES * WW)            // 56320
#define RSTD_OFF (MEAN_OFF + TM)
#define SP_OFF (RSTD_OFF + TM)
#define CB_OFF (SP_OFF + NPAD)
#define SMEM_WORDS (CB_OFF + NPAD)                 // 56992
#define SMEM_BYTES (SMEM_WORDS * 4)                // 227968

__device__ float g_wp[NTILES * NPAD * WROWW];  // pair-interleaved tf32-rounded gamma*W
__device__ float g_sp[NPAD];
__device__ float g_cb[NPAD];

__device__ __forceinline__ uint32_t f2tf32(float f) {
    uint32_t u;
    asm("cvt.rna.tf32.f32 %0, %1;" : "=r"(u) : "f"(f));
    return u;
}
__device__ __forceinline__ void mma_tf32(float* c, const uint32_t* a, const uint32_t* b) {
    asm volatile(
        "mma.sync.aligned.m16n8k8.row.col.f32.tf32.tf32.f32 "
        "{%0,%1,%2,%3}, {%4,%5,%6,%7}, {%8,%9}, {%0,%1,%2,%3};"
        : "+f"(c[0]), "+f"(c[1]), "+f"(c[2]), "+f"(c[3])
        : "r"(a[0]), "r"(a[1]), "r"(a[2]), "r"(a[3]), "r"(b[0]), "r"(b[1]));
}
__device__ __forceinline__ void cp16(float* dst, const float* src) {
    uint32_t d = (uint32_t)__cvta_generic_to_shared(dst);
    asm volatile("cp.async.cg.shared.global [%0], [%1], 16;" :: "r"(d), "l"(src));
}

// ---------------- Prologue: fold gamma into W, pair-interleave, precompute sums ----------------
__global__ void prep_kernel(const float* __restrict__ W,
                            const float* __restrict__ gamma,
                            const float* __restrict__ beta,
                            const float* __restrict__ bias)
{
    __shared__ float rs_[24], rc_[24];
    const int n = blockIdx.x;           // 0..207
    const int k = threadIdx.x;          // 0..767
    const int lane = k & 31, wid = k >> 5;

    float wp = 0.f, cb = 0.f;
    if (n < OUT_DIM) {
        float w = W[n * D_DIM + k];
        wp = __uint_as_float(f2tf32(w * gamma[k]));
        cb = beta[k] * w;
    }
    // pair-interleaved: tile kt, pair p = ks*4+t holds (k, k+4)
    {
        int kt = k >> 5, kk = k & 31;
        int ks = kk >> 3, r8 = kk & 7;
        int p  = ks * 4 + (r8 & 3);
        int hi = r8 >> 2;
        g_wp[(kt * NPAD + n) * WROWW + p * 2 + hi] = wp;
    }
    if (k < 192) {
        int kt = k >> 3;
        g_wp[(kt * NPAD + n) * WROWW + 32 + (k & 7)] = 0.f;
    }

    float s1 = wp;
    #pragma unroll
    for (int off = 16; off; off >>= 1) {
        s1 += __shfl_xor_sync(0xffffffffu, s1, off);
        cb += __shfl_xor_sync(0xffffffffu, cb, off);
    }
    if (lane == 0) { rs_[wid] = s1; rc_[wid] = cb; }
    __syncthreads();
    if (k < 32) {
        float a = (k < 24) ? rs_[k] : 0.f;
        float c = (k < 24) ? rc_[k] : 0.f;
        #pragma unroll
        for (int off = 16; off; off >>= 1) {
            a += __shfl_xor_sync(0xffffffffu, a, off);
            c += __shfl_xor_sync(0xffffffffu, c, off);
        }
        if (k == 0) {
            g_sp[n] = a;
            g_cb[n] = (n < OUT_DIM) ? (c + bias[n]) : 0.f;
        }
    }
}

// ---------------- Main: 16 warps (8M x 2N), split 5/4-stage pipeline ----------------
__global__ __launch_bounds__(NTHREADS, 1)
void ln_gemm_kernel(const float* __restrict__ x, float* __restrict__ out)
{
    extern __shared__ float smem[];
    const int tid  = threadIdx.x;
    const int lane = tid & 31;
    const int wrp  = tid >> 5;             // 0..15
    const long long R0 = (long long)blockIdx.x * TM;

    const int warp_m = wrp & 7;            // 8 M-groups of 16 rows
    const int warp_n = wrp >> 3;           // 2 N halves
    const int grp = lane >> 2;
    const int tig = lane & 3;
    const int nf0 = warp_n * NFRAG;
    const int mrow = warp_m * 16 + grp;    // rows mrow, mrow+8

    if (tid < NPAD) {
        smem[SP_OFF + tid] = g_sp[tid];
        smem[CB_OFF + tid] = g_cb[tid];
    }

    const float* xg = x + R0 * D_DIM;

    auto fill_x = [&](int tile, int stage) {
        float* xd = smem + X_OFF + stage * XW;
        const float* src = xg + tile * BK;
        #pragma unroll
        for (int i = 0; i < 2; i++) {
            int idx = tid + i * NTHREADS;       // 1024 16B chunks
            int r = idx >> 3, c = idx & 7;
            cp16(xd + r * XROWW + c * 4, src + r * D_DIM + c * 4);
        }
    };
    auto fill_w = [&](int tile, int stage) {
        float* wd = smem + W_OFF + stage * WW;
        const float* src = g_wp + tile * NPAD * WROWW;
        #pragma unroll
        for (int i = 0; i < 5; i++) {
            int idx = tid + i * NTHREADS;       // 2080 16B chunks
            if (idx < NPAD * 10) {
                int r = idx / 10, c = idx % 10;
                cp16(wd + r * WROWW + c * 4, src + r * WROWW + c * 4);
            }
        }
    };

    // Prologue groups: g0={x0,x1,W0}, g1={x2,W1}, g2={x3,W2}
    fill_x(0, 0); fill_x(1, 1); fill_w(0, 0);
    asm volatile("cp.async.commit_group;");
    fill_x(2, 2); fill_w(1, 1);
    asm volatile("cp.async.commit_group;");
    fill_x(3, 3); fill_w(2, 2);
    asm volatile("cp.async.commit_group;");

    float acc[NFRAG][4];
    #pragma unroll
    for (int j = 0; j < NFRAG; j++)
        #pragma unroll
        for (int q = 0; q < 4; q++) acc[j][q] = 0.f;

    float ss = 0.f, ss2 = 0.f;
    const int srow = tid >> 2;             // 4 threads per row
    const int soff = (tid & 3) * 8;

    auto stats_round = [&](int stage) {
        float* xb = smem + X_OFF + stage * XW + srow * XROWW + soff;
        #pragma unroll
        for (int i = 0; i < 2; i++) {
            float4* p = reinterpret_cast<float4*>(xb + i * 4);
            float4 v = *p;
            ss  += (v.x + v.y) + (v.z + v.w);
            ss2 += v.x * v.x + v.y * v.y + v.z * v.z + v.w * v.w;
            v.x = __uint_as_float(f2tf32(v.x));
            v.y = __uint_as_float(f2tf32(v.y));
            v.z = __uint_as_float(f2tf32(v.z));
            v.w = __uint_as_float(f2tf32(v.w));
            *p = v;
        }
    };

    // Pre-loop: stats+round tile 0
    asm volatile("cp.async.wait_group 2;");
    __syncthreads();
    stats_round(0);

    int st5 = 0, st4 = 0;
    for (int kt = 0; kt < NTILES; kt++) {
        asm volatile("cp.async.wait_group 2;");
        __syncthreads();

        // refill early: x tile kt+4, W tile kt+3
        {
            int sx = st5 + 4; if (sx >= 5) sx -= 5;
            int sw = st4 + 3; if (sw >= 4) sw -= 4;
            if (kt + 4 < NTILES) fill_x(kt + 4, sx);
            if (kt + 3 < NTILES) fill_w(kt + 3, sw);
            asm volatile("cp.async.commit_group;");
        }

        // stats + roundback tile kt+1 (distinct stage from MMA below)
        if (kt + 1 < NTILES) {
            int sn = st5 + 1; if (sn >= 5) sn -= 5;
            stats_round(sn);
        }

        // MMA tile kt
        {
            const float* xs = smem + X_OFF + st5 * XW;
            const float* ws = smem + W_OFF + st4 * WW;
            #pragma unroll
            for (int ks = 0; ks < 4; ks++) {
                const int kc = ks * 8 + tig;
                uint32_t a[4];
                a[0] = __float_as_uint(xs[mrow * XROWW + kc]);
                a[1] = __float_as_uint(xs[(mrow + 8) * XROWW + kc]);
                a[2] = __float_as_uint(xs[mrow * XROWW + kc + 4]);
                a[3] = __float_as_uint(xs[(mrow + 8) * XROWW + kc + 4]);
                const int pc = (ks * 4 + tig) * 2;
                #pragma unroll
                for (int j = 0; j < NFRAG; j++) {
                    int nb = (nf0 + j) * 8 + grp;
                    float2 bv = *reinterpret_cast<const float2*>(ws + nb * WROWW + pc);
                    uint32_t b[2] = { __float_as_uint(bv.x), __float_as_uint(bv.y) };
                    mma_tf32(acc[j], a, b);
                }
            }
        }

        if (++st5 == 5) st5 = 0;
        if (++st4 == 4) st4 = 0;
    }

    // Finalize stats: 4 threads per row
    float stot  = ss, stot2 = ss2;
    #pragma unroll
    for (int off = 1; off < 4; off <<= 1) {
        stot  += __shfl_xor_sync(0xffffffffu, stot,  off);
        stot2 += __shfl_xor_sync(0xffffffffu, stot2, off);
    }
    if ((tid & 3) == 0) {
        int r = tid >> 2;
        float m   = stot * (1.0f / D_DIM);
        float var = fmaxf(stot2 * (1.0f / D_DIM) - m * m, 0.0f);
        smem[MEAN_OFF + r] = m;
        smem[RSTD_OFF + r] = rsqrtf(var + 1e-6f);
    }
    __syncthreads();

    // Epilogue: out = rs*acc + (-rs*mu*S' + cb)
    {
        const float rs0 = smem[RSTD_OFF + mrow];
        const float rs1 = smem[RSTD_OFF + mrow + 8];
        const float nmu0 = -smem[MEAN_OFF + mrow] * rs0;
        const float nmu1 = -smem[MEAN_OFF + mrow + 8] * rs1;
        #pragma unroll
        for (int j = 0; j < NFRAG; j++) {
            int n = (nf0 + j) * 8 + 2 * tig;
            if (n < OUT_DIM) {
                float sp0 = smem[SP_OFF + n],  sp1 = smem[SP_OFF + n + 1];
                float cb0 = smem[CB_OFF + n],  cb1 = smem[CB_OFF + n + 1];
                long long row0 = R0 + mrow;
                float2 v0 = make_float2(fmaf(rs0, acc[j][0], fmaf(nmu0, sp0, cb0)),
                                        fmaf(rs0, acc[j][1], fmaf(nmu0, sp1, cb1)));
                float2 v1 = make_float2(fmaf(rs1, acc[j][2], fmaf(nmu1, sp0, cb0)),
                                        fmaf(rs1, acc[j][3], fmaf(nmu1, sp1, cb1)));
                *reinterpret_cast<float2*>(out + row0 * OUT_DIM + n)       = v0;
                *reinterpret_cast<float2*>(out + (row0 + 8) * OUT_DIM + n) = v1;
            }
        }
    }
}

extern "C" void kernel_launch(void* const* d_in, const int* in_sizes, int n_in,
                              void* d_out, int out_size) {
    const float* x     = (const float*)d_in[0];
    const float* gamma = (const float*)d_in[1];
    const float* beta  = (const float*)d_in[2];
    const float* W     = (const float*)d_in[3];
    const float* b     = (const float*)d_in[4];
    float* out = (float*)d_out;

    cudaFuncSetAttribute(ln_gemm_kernel,
                         cudaFuncAttributeMaxDynamicSharedMemorySize, SMEM_BYTES);

    const int rows = in_sizes[0] / D_DIM;   // 65536
    prep_kernel<<<NPAD, D_DIM>>>(W, gamma, beta, b);
    ln_gemm_kernel<<<rows / TM, NTHREADS, SMEM_BYTES>>>(x, out);
}

// round 12
// speedup vs baseline: 1.7877x; 1.7877x over previous
#include <cuda_runtime.h>
#include <cstdint>

#define D_DIM 768
#define OUT_DIM 196
#define NPAD 208
#define TM 128
#define NH 104                         // N columns per CTA (half of 208)
#define BK 32
#define NTILES 24
#define NFRAG 13                       // 13*8 = 104 = NH

#define XROWW 36                       // x row stride (words)
#define XW (TM * XROWW)                // 4608 words / stage
#define WROWW 40                       // W row stride (words) = 20 float2
#define WW (NH * WROWW)                // 4160 words / stage
#define XSTAGES 4
#define WSTAGES 2

#define X_OFF 0
#define W_OFF (XSTAGES * XW)           // 18432
#define MEAN_OFF (W_OFF + WSTAGES * WW) // 26752
#define RSTD_OFF (MEAN_OFF + TM)
#define SP_OFF (RSTD_OFF + TM)
#define CB_OFF (SP_OFF + NH)
#define SMEM_WORDS (CB_OFF + NH)       // 27216
#define SMEM_BYTES (SMEM_WORDS * 4)    // 108864 -> 2 CTAs/SM

__device__ float g_wp[NTILES * NPAD * WROWW];  // pair-interleaved tf32-rounded gamma*W
__device__ float g_sp[NPAD];
__device__ float g_cb[NPAD];

__device__ __forceinline__ uint32_t f2tf32(float f) {
    uint32_t u;
    asm("cvt.rna.tf32.f32 %0, %1;" : "=r"(u) : "f"(f));
    return u;
}
__device__ __forceinline__ void mma_tf32(float* c, const uint32_t* a, const uint32_t* b) {
    asm volatile(
        "mma.sync.aligned.m16n8k8.row.col.f32.tf32.tf32.f32 "
        "{%0,%1,%2,%3}, {%4,%5,%6,%7}, {%8,%9}, {%0,%1,%2,%3};"
        : "+f"(c[0]), "+f"(c[1]), "+f"(c[2]), "+f"(c[3])
        : "r"(a[0]), "r"(a[1]), "r"(a[2]), "r"(a[3]), "r"(b[0]), "r"(b[1]));
}
__device__ __forceinline__ void cp16(float* dst, const float* src) {
    uint32_t d = (uint32_t)__cvta_generic_to_shared(dst);
    asm volatile("cp.async.cg.shared.global [%0], [%1], 16;" :: "r"(d), "l"(src));
}

// ---------------- Prologue: fold gamma into W, pair-interleave, precompute sums ----------------
__global__ void prep_kernel(const float* __restrict__ W,
                            const float* __restrict__ gamma,
                            const float* __restrict__ beta,
                            const float* __restrict__ bias)
{
    __shared__ float rs_[24], rc_[24];
    const int n = blockIdx.x;           // 0..207
    const int k = threadIdx.x;          // 0..767
    const int lane = k & 31, wid = k >> 5;

    float wp = 0.f, cb = 0.f;
    if (n < OUT_DIM) {
        float w = W[n * D_DIM + k];
        wp = __uint_as_float(f2tf32(w * gamma[k]));
        cb = beta[k] * w;
    }
    // pair-interleaved: tile kt, pair p = ks*4+t holds (k, k+4)
    {
        int kt = k >> 5, kk = k & 31;
        int ks = kk >> 3, r8 = kk & 7;
        int p  = ks * 4 + (r8 & 3);
        int hi = r8 >> 2;
        g_wp[(kt * NPAD + n) * WROWW + p * 2 + hi] = wp;
    }
    if (k < 192) {
        int kt = k >> 3;
        g_wp[(kt * NPAD + n) * WROWW + 32 + (k & 7)] = 0.f;
    }

    float s1 = wp;
    #pragma unroll
    for (int off = 16; off; off >>= 1) {
        s1 += __shfl_xor_sync(0xffffffffu, s1, off);
        cb += __shfl_xor_sync(0xffffffffu, cb, off);
    }
    if (lane == 0) { rs_[wid] = s1; rc_[wid] = cb; }
    __syncthreads();
    if (k < 32) {
        float a = (k < 24) ? rs_[k] : 0.f;
        float c = (k < 24) ? rc_[k] : 0.f;
        #pragma unroll
        for (int off = 16; off; off >>= 1) {
            a += __shfl_xor_sync(0xffffffffu, a, off);
            c += __shfl_xor_sync(0xffffffffu, c, off);
        }
        if (k == 0) {
            g_sp[n] = a;
            g_cb[n] = (n < OUT_DIM) ? (c + bias[n]) : 0.f;
        }
    }
}

// ---------------- Main: N-split CTAs (2/SM), 8 warps, warp-private stats ----------------
__global__ __launch_bounds__(256, 2)
void ln_gemm_kernel(const float* __restrict__ x, float* __restrict__ out)
{
    extern __shared__ float smem[];
    const int tid  = threadIdx.x;
    const int lane = tid & 31;
    const int wrp  = tid >> 5;                 // 0..7 : M-warp (16 rows each)
    const int rowblk = blockIdx.x >> 1;
    const int nh     = blockIdx.x & 1;         // N half
    const long long R0 = (long long)rowblk * TM;

    const int grp = lane >> 2;
    const int tig = lane & 3;
    const int mrow = wrp * 16 + grp;           // rows mrow, mrow+8

    if (tid < NH) {
        smem[SP_OFF + tid] = g_sp[nh * NH + tid];
        smem[CB_OFF + tid] = g_cb[nh * NH + tid];
    }

    const float* xg = x + R0 * D_DIM;
    const float* wg = g_wp + (long long)nh * NH * WROWW;

    auto fill_x = [&](int tile, int stage) {
        float* xd = smem + X_OFF + stage * XW;
        const float* src = xg + tile * BK;
        #pragma unroll
        for (int i = 0; i < 4; i++) {
            int idx = tid + i * 256;           // 1024 16B chunks
            int r = idx >> 3, c = idx & 7;
            cp16(xd + r * XROWW + c * 4, src + r * D_DIM + c * 4);
        }
    };
    auto fill_w = [&](int tile, int stage) {
        float* wd = smem + W_OFF + stage * WW;
        const float* src = wg + (long long)tile * NPAD * WROWW;
        #pragma unroll
        for (int i = 0; i < 5; i++) {
            int idx = tid + i * 256;           // 1040 16B chunks
            if (idx < NH * 10) {
                int r = idx / 10, c = idx % 10;
                cp16(wd + r * WROWW + c * 4, src + r * WROWW + c * 4);
            }
        }
    };

    // Prologue: G1={x0,W0}, G2={x1,W1}, G3={x2}
    fill_x(0, 0); fill_w(0, 0);
    asm volatile("cp.async.commit_group;");
    fill_x(1, 1); fill_w(1, 1);
    asm volatile("cp.async.commit_group;");
    fill_x(2, 2);
    asm volatile("cp.async.commit_group;");

    float acc[NFRAG][4];
    #pragma unroll
    for (int j = 0; j < NFRAG; j++)
        #pragma unroll
        for (int q = 0; q < 4; q++) acc[j][q] = 0.f;

    // warp-private stats: lane handles row wrp*16 + (lane>>1), cols half (lane&1)
    float ss = 0.f, ss2 = 0.f;
    const int srow = wrp * 16 + (lane >> 1);
    const int soff = (lane & 1) * 16;

    for (int kt = 0; kt < NTILES; kt++) {
        const int st4 = kt & 3;
        const int st2 = kt & 1;

        asm volatile("cp.async.wait_group 1;");
        __syncthreads();

        // refills: W tile kt+1 -> stage (kt+1)&1 ; x tile kt+3 -> stage (kt+3)&3
        if (kt >= 1 && kt + 1 < NTILES) fill_w(kt + 1, (kt + 1) & 1);
        asm volatile("cp.async.commit_group;");        // Gw
        if (kt + 3 < NTILES) fill_x(kt + 3, (kt + 3) & 3);
        asm volatile("cp.async.commit_group;");        // Gx (newest)

        // stats + tf32 roundback of own warp's rows (tile kt)
        {
            float* xb = smem + X_OFF + st4 * XW + srow * XROWW + soff;
            #pragma unroll
            for (int i = 0; i < 4; i++) {
                float4* p = reinterpret_cast<float4*>(xb + i * 4);
                float4 v = *p;
                ss  += (v.x + v.y) + (v.z + v.w);
                ss2 += v.x * v.x + v.y * v.y + v.z * v.z + v.w * v.w;
                v.x = __uint_as_float(f2tf32(v.x));
                v.y = __uint_as_float(f2tf32(v.y));
                v.z = __uint_as_float(f2tf32(v.z));
                v.w = __uint_as_float(f2tf32(v.w));
                *p = v;
            }
        }
        __syncwarp();

        // MMA tile kt
        {
            const float* xs = smem + X_OFF + st4 * XW;
            const float* ws = smem + W_OFF + st2 * WW;
            #pragma unroll
            for (int ks = 0; ks < 4; ks++) {
                const int kc = ks * 8 + tig;
                uint32_t a[4];
                a[0] = __float_as_uint(xs[mrow * XROWW + kc]);
                a[1] = __float_as_uint(xs[(mrow + 8) * XROWW + kc]);
                a[2] = __float_as_uint(xs[mrow * XROWW + kc + 4]);
                a[3] = __float_as_uint(xs[(mrow + 8) * XROWW + kc + 4]);
                const int pc = (ks * 4 + tig) * 2;
                #pragma unroll
                for (int j = 0; j < NFRAG; j++) {
                    int nb = j * 8 + grp;
                    float2 bv = *reinterpret_cast<const float2*>(ws + nb * WROWW + pc);
                    uint32_t b[2] = { __float_as_uint(bv.x), __float_as_uint(bv.y) };
                    mma_tf32(acc[j], a, b);
                }
            }
        }
    }

    // Finalize stats (pairs of lanes own one row)
    float stot  = ss  + __shfl_xor_sync(0xffffffffu, ss,  1);
    float stot2 = ss2 + __shfl_xor_sync(0xffffffffu, ss2, 1);
    if ((lane & 1) == 0) {
        int r = srow;
        float m   = stot * (1.0f / D_DIM);
        float var = fmaxf(stot2 * (1.0f / D_DIM) - m * m, 0.0f);
        smem[MEAN_OFF + r] = m;
        smem[RSTD_OFF + r] = rsqrtf(var + 1e-6f);
    }
    __syncwarp();   // stats consumed only by the same warp

    // Epilogue: out = rs*acc + (-rs*mu*S' + cb)
    {
        const float rs0 = smem[RSTD_OFF + mrow];
        const float rs1 = smem[RSTD_OFF + mrow + 8];
        const float nmu0 = -smem[MEAN_OFF + mrow] * rs0;
        const float nmu1 = -smem[MEAN_OFF + mrow + 8] * rs1;
        #pragma unroll
        for (int j = 0; j < NFRAG; j++) {
            int nl = j * 8 + 2 * tig;
            int ng = nh * NH + nl;
            if (ng < OUT_DIM) {
                float sp0 = smem[SP_OFF + nl],  sp1 = smem[SP_OFF + nl + 1];
                float cb0 = smem[CB_OFF + nl],  cb1 = smem[CB_OFF + nl + 1];
                long long row0 = R0 + mrow;
                float2 v0 = make_float2(fmaf(rs0, acc[j][0], fmaf(nmu0, sp0, cb0)),
                                        fmaf(rs0, acc[j][1], fmaf(nmu0, sp1, cb1)));
                float2 v1 = make_float2(fmaf(rs1, acc[j][2], fmaf(nmu1, sp0, cb0)),
                                        fmaf(rs1, acc[j][3], fmaf(nmu1, sp1, cb1)));
                *reinterpret_cast<float2*>(out + row0 * OUT_DIM + ng)       = v0;
                *reinterpret_cast<float2*>(out + (row0 + 8) * OUT_DIM + ng) = v1;
            }
        }
    }
}

extern "C" void kernel_launch(void* const* d_in, const int* in_sizes, int n_in,
                              void* d_out, int out_size) {
    const float* x     = (const float*)d_in[0];
    const float* gamma = (const float*)d_in[1];
    const float* beta  = (const float*)d_in[2];
    const float* W     = (const float*)d_in[3];
    const float* b     = (const float*)d_in[4];
    float* out = (float*)d_out;

    cudaFuncSetAttribute(ln_gemm_kernel,
                         cudaFuncAttributeMaxDynamicSharedMemorySize, SMEM_BYTES);

    const int rows = in_sizes[0] / D_DIM;   // 65536
    prep_kernel<<<NPAD, D_DIM>>>(W, gamma, beta, b);
    ln_gemm_kernel<<<(rows / TM) * 2, 256, SMEM_BYTES>>>(x, out);
}

// round 13
// speedup vs baseline: 1.8348x; 1.0263x over previous
#include <cuda_runtime.h>
#include <cstdint>

#define D_DIM 768
#define OUT_DIM 196
#define NPAD 208
#define TM 128
#define BK 32
#define NTILES 24
#define NFRAG 13

#define XROWW 36                       // x row stride (words): conflict-free frag reads
#define XW (TM * XROWW)                // 4608 words / stage
#define WROWW 40                       // W row stride (words) = 20 float2: CF per phase
#define WW (NPAD * WROWW)              // 8320 words / stage
#define XSTAGES 4
#define WSTAGES 4

#define X_OFF 0
#define W_OFF (XSTAGES * XW)                 // 18432
#define SP_OFF (W_OFF + WSTAGES * WW)        // 51712
#define CB_OFF (SP_OFF + NPAD)
#define SMEM_WORDS (CB_OFF + NPAD)           // 52128
#define SMEM_BYTES (SMEM_WORDS * 4)          // 208512 (< 232448)

__device__ float g_wp[NTILES * NPAD * WROWW];  // pair-interleaved tf32-rounded gamma*W
__device__ float g_sp[NPAD];
__device__ float g_cb[NPAD];

__device__ __forceinline__ uint32_t f2tf32(float f) {
    uint32_t u;
    asm("cvt.rna.tf32.f32 %0, %1;" : "=r"(u) : "f"(f));
    return u;
}
__device__ __forceinline__ void mma_tf32(float* c, const uint32_t* a, const uint32_t* b) {
    asm volatile(
        "mma.sync.aligned.m16n8k8.row.col.f32.tf32.tf32.f32 "
        "{%0,%1,%2,%3}, {%4,%5,%6,%7}, {%8,%9}, {%0,%1,%2,%3};"
        : "+f"(c[0]), "+f"(c[1]), "+f"(c[2]), "+f"(c[3])
        : "r"(a[0]), "r"(a[1]), "r"(a[2]), "r"(a[3]), "r"(b[0]), "r"(b[1]));
}
__device__ __forceinline__ void cp16(float* dst, const float* src) {
    uint32_t d = (uint32_t)__cvta_generic_to_shared(dst);
    asm volatile("cp.async.cg.shared.global [%0], [%1], 16;" :: "r"(d), "l"(src));
}

// ---------------- Prologue: fold gamma into W, pair-interleave, precompute sums ----------------
__global__ void prep_kernel(const float* __restrict__ W,
                            const float* __restrict__ gamma,
                            const float* __restrict__ beta,
                            const float* __restrict__ bias)
{
    __shared__ float rs_[24], rc_[24];
    const int n = blockIdx.x;           // 0..207
    const int k = threadIdx.x;          // 0..767
    const int lane = k & 31, wid = k >> 5;

    float wp = 0.f, cb = 0.f;
    if (n < OUT_DIM) {
        float w = W[n * D_DIM + k];
        wp = __uint_as_float(f2tf32(w * gamma[k]));
        cb = beta[k] * w;
    }
    // pair-interleaved: tile kt, pair p = ks*4+t holds (k, k+4)
    {
        int kt = k >> 5, kk = k & 31;
        int ks = kk >> 3, r8 = kk & 7;
        int p  = ks * 4 + (r8 & 3);
        int hi = r8 >> 2;
        g_wp[(kt * NPAD + n) * WROWW + p * 2 + hi] = wp;
    }
    if (k < 192) {
        int kt = k >> 3;
        g_wp[(kt * NPAD + n) * WROWW + 32 + (k & 7)] = 0.f;
    }

    float s1 = wp;
    #pragma unroll
    for (int off = 16; off; off >>= 1) {
        s1 += __shfl_xor_sync(0xffffffffu, s1, off);
        cb += __shfl_xor_sync(0xffffffffu, cb, off);
    }
    if (lane == 0) { rs_[wid] = s1; rc_[wid] = cb; }
    __syncthreads();
    if (k < 32) {
        float a = (k < 24) ? rs_[k] : 0.f;
        float c = (k < 24) ? rc_[k] : 0.f;
        #pragma unroll
        for (int off = 16; off; off >>= 1) {
            a += __shfl_xor_sync(0xffffffffu, a, off);
            c += __shfl_xor_sync(0xffffffffu, c, off);
        }
        if (k == 0) {
            g_sp[n] = a;
            g_cb[n] = (n < OUT_DIM) ? (c + bias[n]) : 0.f;
        }
    }
}

// ---------------- Main: 8 warps (4M x 2N), 32-row warp tiles, register stats ----------------
__global__ __launch_bounds__(256, 1)
void ln_gemm_kernel(const float* __restrict__ x, float* __restrict__ out)
{
    extern __shared__ float smem[];
    const int tid  = threadIdx.x;
    const int lane = tid & 31;
    const int wrp  = tid >> 5;                 // 0..7
    const long long R0 = (long long)blockIdx.x * TM;

    const int warp_m = wrp & 3;                // 4 M-groups of 32 rows
    const int warp_n = wrp >> 2;               // 2 N halves of 104
    const int grp = lane >> 2;
    const int tig = lane & 3;
    const int nf0 = warp_n * NFRAG;
    const int mrow = warp_m * 32 + grp;        // base row for this lane

    if (tid < NPAD) {
        smem[SP_OFF + tid] = g_sp[tid];
        smem[CB_OFF + tid] = g_cb[tid];
    }

    const float* xg = x + R0 * D_DIM;

    auto fill_x = [&](int tile, int stage) {
        float* xd = smem + X_OFF + stage * XW;
        const float* src = xg + tile * BK;
        #pragma unroll
        for (int i = 0; i < 4; i++) {
            int idx = tid + i * 256;           // 1024 16B chunks
            int r = idx >> 3, c = idx & 7;
            cp16(xd + r * XROWW + c * 4, src + r * D_DIM + c * 4);
        }
    };
    auto fill_w = [&](int tile, int stage) {
        float* wd = smem + W_OFF + stage * WW;
        const float* src = g_wp + (long long)tile * NPAD * WROWW;
        #pragma unroll
        for (int i = 0; i < 9; i++) {
            int idx = tid + i * 256;           // 2080 16B chunks
            if (idx < NPAD * 10) {
                int r = idx / 10, c = idx % 10;
                cp16(wd + r * WROWW + c * 4, src + r * WROWW + c * 4);
            }
        }
    };

    // Prologue: 3 groups {x_i, W_i}
    fill_x(0, 0); fill_w(0, 0);
    asm volatile("cp.async.commit_group;");
    fill_x(1, 1); fill_w(1, 1);
    asm volatile("cp.async.commit_group;");
    fill_x(2, 2); fill_w(2, 2);
    asm volatile("cp.async.commit_group;");

    float acc[2][NFRAG][4];
    #pragma unroll
    for (int s = 0; s < 2; s++)
        #pragma unroll
        for (int j = 0; j < NFRAG; j++)
            #pragma unroll
            for (int q = 0; q < 4; q++) acc[s][j][q] = 0.f;

    // register stats: per (s, h) accumulators; rows mrow + s*16 + h*8
    float ss[2][2]  = {{0.f, 0.f}, {0.f, 0.f}};
    float sq[2][2]  = {{0.f, 0.f}, {0.f, 0.f}};

    for (int kt = 0; kt < NTILES; kt++) {
        const int st = kt & 3;
        asm volatile("cp.async.wait_group 2;");
        __syncthreads();

        // refill stage (kt+3)&3 (consumed at iter kt-1)
        if (kt + 3 < NTILES) {
            fill_x(kt + 3, (kt + 3) & 3);
            fill_w(kt + 3, (kt + 3) & 3);
        }
        asm volatile("cp.async.commit_group;");

        const float* xs = smem + X_OFF + st * XW;
        const float* ws = smem + W_OFF + st * WW;

        #pragma unroll
        for (int ks = 0; ks < 4; ks++) {
            const int kc = ks * 8 + tig;
            // raw A-frags
            float ar[2][4];
            #pragma unroll
            for (int s = 0; s < 2; s++) {
                const int r = mrow + s * 16;
                ar[s][0] = xs[r * XROWW + kc];
                ar[s][1] = xs[(r + 8) * XROWW + kc];
                ar[s][2] = xs[r * XROWW + kc + 4];
                ar[s][3] = xs[(r + 8) * XROWW + kc + 4];
            }
            // stats on raw values (each (row,col) counted exactly once per warp)
            #pragma unroll
            for (int s = 0; s < 2; s++) {
                ss[s][0] += ar[s][0] + ar[s][2];
                ss[s][1] += ar[s][1] + ar[s][3];
                sq[s][0] += ar[s][0] * ar[s][0] + ar[s][2] * ar[s][2];
                sq[s][1] += ar[s][1] * ar[s][1] + ar[s][3] * ar[s][3];
            }
            // cvt to tf32-RNA in place
            uint32_t a[2][4];
            #pragma unroll
            for (int s = 0; s < 2; s++)
                #pragma unroll
                for (int q = 0; q < 4; q++) a[s][q] = f2tf32(ar[s][q]);

            const int pc = (ks * 4 + tig) * 2;
            #pragma unroll
            for (int j = 0; j < NFRAG; j++) {
                int nb = (nf0 + j) * 8 + grp;
                float2 bv = *reinterpret_cast<const float2*>(ws + nb * WROWW + pc);
                uint32_t b[2] = { __float_as_uint(bv.x), __float_as_uint(bv.y) };
                mma_tf32(acc[0][j], a[0], b);
                mma_tf32(acc[1][j], a[1], b);
            }
        }
    }

    // Finalize stats: sum over tig (lanes sharing grp)
    float rs_[2][2], nmu[2][2];
    #pragma unroll
    for (int s = 0; s < 2; s++)
        #pragma unroll
        for (int h = 0; h < 2; h++) {
            float t1 = ss[s][h], t2 = sq[s][h];
            #pragma unroll
            for (int off = 1; off < 4; off <<= 1) {
                t1 += __shfl_xor_sync(0xffffffffu, t1, off);
                t2 += __shfl_xor_sync(0xffffffffu, t2, off);
            }
            float m   = t1 * (1.0f / D_DIM);
            float var = fmaxf(t2 * (1.0f / D_DIM) - m * m, 0.0f);
            float r   = rsqrtf(var + 1e-6f);
            rs_[s][h] = r;
            nmu[s][h] = -m * r;
        }

    // Epilogue: out = rs*acc + (-rs*mu*S' + cb)
    #pragma unroll
    for (int s = 0; s < 2; s++) {
        const float r0 = rs_[s][0], u0 = nmu[s][0];
        const float r1 = rs_[s][1], u1 = nmu[s][1];
        #pragma unroll
        for (int j = 0; j < NFRAG; j++) {
            int n = (nf0 + j) * 8 + 2 * tig;
            if (n < OUT_DIM) {
                float sp0 = smem[SP_OFF + n], sp1 = smem[SP_OFF + n + 1];
                float cb0 = smem[CB_OFF + n], cb1 = smem[CB_OFF + n + 1];
                long long row0 = R0 + mrow + s * 16;
                float2 v0 = make_float2(fmaf(r0, acc[s][j][0], fmaf(u0, sp0, cb0)),
                                        fmaf(r0, acc[s][j][1], fmaf(u0, sp1, cb1)));
                float2 v1 = make_float2(fmaf(r1, acc[s][j][2], fmaf(u1, sp0, cb0)),
                                        fmaf(r1, acc[s][j][3], fmaf(u1, sp1, cb1)));
                *reinterpret_cast<float2*>(out + row0 * OUT_DIM + n)       = v0;
                *reinterpret_cast<float2*>(out + (row0 + 8) * OUT_DIM + n) = v1;
            }
        }
    }
}

extern "C" void kernel_launch(void* const* d_in, const int* in_sizes, int n_in,
                              void* d_out, int out_size) {
    const float* x     = (const float*)d_in[0];
    const float* gamma = (const float*)d_in[1];
    const float* beta  = (const float*)d_in[2];
    const float* W     = (const float*)d_in[3];
    const float* b     = (const float*)d_in[4];
    float* out = (float*)d_out;

    cudaFuncSetAttribute(ln_gemm_kernel,
                         cudaFuncAttributeMaxDynamicSharedMemorySize, SMEM_BYTES);

    const int rows = in_sizes[0] / D_DIM;   // 65536
    prep_kernel<<<NPAD, D_DIM>>>(W, gamma, beta, b);
    ln_gemm_kernel<<<rows / TM, 256, SMEM_BYTES>>>(x, out);
}

// round 15
// speedup vs baseline: 2.6413x; 1.4396x over previous
#include <cuda_runtime.h>
#include <cuda_fp16.h>
#include <cstdint>

#define D_DIM 768
#define OUT_DIM 196
#define NPAD 208
#define TM 128
#define BK 32
#define NTILES 24
#define NFRAG 13

#define XROWW 40                       // x row stride (words): 8g+2t conflict-free float2
#define XW (TM * XROWW)                // 5120 words / stage
#define WROWW 24                       // W words per n per k-tile (16 data + 8 pad)
#define WW (NPAD * WROWW)              // 4992 words / stage
#define STAGES 4

#define X_OFF 0
#define W_OFF (STAGES * XW)            // 20480
#define SP_OFF (W_OFF + STAGES * WW)   // 40448
#define CB_OFF (SP_OFF + NPAD)
#define SMEM_WORDS (CB_OFF + NPAD)     // 40864
#define SMEM_BYTES (SMEM_WORDS * 4)    // 163456

__device__ __half g_wph[NTILES * NPAD * 32];  // fp16 gamma*W, frag-packed per k-tile
__device__ float  g_sp[NPAD];                 // row sums of fp16-rounded gamma*W
__device__ float  g_cb[NPAD];                 // beta.W + bias

__device__ __forceinline__ uint32_t pack_h2(float lo, float hi) {
    uint32_t u;
    asm("cvt.rn.f16x2.f32 %0, %1, %2;" : "=r"(u) : "f"(hi), "f"(lo));
    return u;
}
__device__ __forceinline__ void mma_f16(float* c, const uint32_t* a, const uint32_t* b) {
    asm volatile(
        "mma.sync.aligned.m16n8k16.row.col.f32.f16.f16.f32 "
        "{%0,%1,%2,%3}, {%4,%5,%6,%7}, {%8,%9}, {%0,%1,%2,%3};"
        : "+f"(c[0]), "+f"(c[1]), "+f"(c[2]), "+f"(c[3])
        : "r"(a[0]), "r"(a[1]), "r"(a[2]), "r"(a[3]), "r"(b[0]), "r"(b[1]));
}
__device__ __forceinline__ void cp16(void* dst, const void* src) {
    uint32_t d = (uint32_t)__cvta_generic_to_shared(dst);
    asm volatile("cp.async.cg.shared.global [%0], [%1], 16;" :: "r"(d), "l"(src));
}

// ---------------- Prologue: fold gamma into W (fp16), frag-pack, precompute sums ----------------
__global__ void prep_kernel(const float* __restrict__ W,
                            const float* __restrict__ gamma,
                            const float* __restrict__ beta,
                            const float* __restrict__ bias)
{
    __shared__ float rs_[24], rc_[24];
    const int n = blockIdx.x;           // 0..207
    const int k = threadIdx.x;          // 0..767
    const int lane = k & 31, wid = k >> 5;

    float wg = 0.f, cb = 0.f;
    if (n < OUT_DIM) {
        float w = W[n * D_DIM + k];
        wg = w * gamma[k];
        cb = beta[k] * w;
    }
    __half wph = __float2half_rn(wg);
    // frag-packed layout: k-tile kt (32 k), chunk c = (k%32)/16, j = k%16
    // word = ((j&7)>>1)*2 + (j>>3), halfword = j&1
    {
        int kt = k >> 5, kk = k & 31;
        int c  = kk >> 4, j = kk & 15;
        int word = ((j & 7) >> 1) * 2 + (j >> 3);
        g_wph[(kt * NPAD + n) * 32 + (c * 8 + word) * 2 + (j & 1)] = wph;
    }

    float s1 = __half2float(wph);       // sum the fp16-rounded values
    #pragma unroll
    for (int off = 16; off; off >>= 1) {
        s1 += __shfl_xor_sync(0xffffffffu, s1, off);
        cb += __shfl_xor_sync(0xffffffffu, cb, off);
    }
    if (lane == 0) { rs_[wid] = s1; rc_[wid] = cb; }
    __syncthreads();
    if (k < 32) {
        float a = (k < 24) ? rs_[k] : 0.f;
        float c = (k < 24) ? rc_[k] : 0.f;
        #pragma unroll
        for (int off = 16; off; off >>= 1) {
            a += __shfl_xor_sync(0xffffffffu, a, off);
            c += __shfl_xor_sync(0xffffffffu, c, off);
        }
        if (k == 0) {
            g_sp[n] = a;
            g_cb[n] = (n < OUT_DIM) ? (c + bias[n]) : 0.f;
        }
    }
}

// ---------------- Main: 8 warps (4M x 2N), fp16 k16 MMA, register stats ----------------
__global__ __launch_bounds__(256, 1)
void ln_gemm_kernel(const float* __restrict__ x, float* __restrict__ out)
{
    extern __shared__ float smem[];
    const int tid  = threadIdx.x;
    const int lane = tid & 31;
    const int wrp  = tid >> 5;                 // 0..7
    const long long R0 = (long long)blockIdx.x * TM;

    const int warp_m = wrp & 3;                // 4 M-groups of 32 rows
    const int warp_n = wrp >> 2;               // 2 N halves of 104
    const int grp = lane >> 2;
    const int tig = lane & 3;
    const int nf0 = warp_n * NFRAG;
    const int mrow = warp_m * 32 + grp;

    if (tid < NPAD) {
        smem[SP_OFF + tid] = g_sp[tid];
        smem[CB_OFF + tid] = g_cb[tid];
    }

    const float* xg = x + R0 * D_DIM;

    auto fill_x = [&](int tile, int stage) {
        float* xd = smem + X_OFF + stage * XW;
        const float* src = xg + tile * BK;
        #pragma unroll
        for (int i = 0; i < 4; i++) {
            int idx = tid + i * 256;           // 1024 16B chunks
            int r = idx >> 3, c = idx & 7;
            cp16(xd + r * XROWW + c * 4, src + r * D_DIM + c * 4);
        }
    };
    auto fill_w = [&](int tile, int stage) {
        float* wd = smem + W_OFF + stage * WW;
        const __half* src = g_wph + (long long)tile * NPAD * 32;
        #pragma unroll
        for (int i = 0; i < 4; i++) {
            int idx = tid + i * 256;           // 832 16B chunks
            if (idx < NPAD * 4) {
                int r = idx >> 2, c = idx & 3;
                cp16(wd + r * WROWW + c * 4, src + r * 32 + c * 8);
            }
        }
    };

    // Prologue: 3 groups {x_i, W_i}
    fill_x(0, 0); fill_w(0, 0);
    asm volatile("cp.async.commit_group;");
    fill_x(1, 1); fill_w(1, 1);
    asm volatile("cp.async.commit_group;");
    fill_x(2, 2); fill_w(2, 2);
    asm volatile("cp.async.commit_group;");

    float acc[2][NFRAG][4];
    #pragma unroll
    for (int s = 0; s < 2; s++)
        #pragma unroll
        for (int j = 0; j < NFRAG; j++)
            #pragma unroll
            for (int q = 0; q < 4; q++) acc[s][j][q] = 0.f;

    // register stats: rows mrow + s*16 + h*8
    float ss[2][2] = {{0.f, 0.f}, {0.f, 0.f}};
    float sq[2][2] = {{0.f, 0.f}, {0.f, 0.f}};

    for (int kt = 0; kt < NTILES; kt++) {
        const int st = kt & 3;
        asm volatile("cp.async.wait_group 2;");
        __syncthreads();

        if (kt + 3 < NTILES) {
            fill_x(kt + 3, (kt + 3) & 3);
            fill_w(kt + 3, (kt + 3) & 3);
        }
        asm volatile("cp.async.commit_group;");

        const float* xs = smem + X_OFF + st * XW;
        const uint32_t* ws = reinterpret_cast<const uint32_t*>(smem + W_OFF + st * WW);

        #pragma unroll
        for (int c = 0; c < 2; c++) {          // two k16 chunks
            // B frags: one LDS.64 each (f16x2 pair), conflict-free
            uint32_t b[NFRAG][2];
            #pragma unroll
            for (int j = 0; j < NFRAG; j++) {
                const int nb = (nf0 + j) * 8 + grp;
                uint2 bv = *reinterpret_cast<const uint2*>(ws + nb * WROWW + c * 8 + tig * 2);
                b[j][0] = bv.x; b[j][1] = bv.y;
            }
            // A frags: fp32 pairs -> stats -> f16x2
            uint32_t a[2][4];
            #pragma unroll
            for (int s = 0; s < 2; s++) {
                const int r = mrow + s * 16;
                const float* base = xs + c * 16 + tig * 2;
                float2 v00 = *reinterpret_cast<const float2*>(base + r * XROWW);
                float2 v10 = *reinterpret_cast<const float2*>(base + (r + 8) * XROWW);
                float2 v01 = *reinterpret_cast<const float2*>(base + r * XROWW + 8);
                float2 v11 = *reinterpret_cast<const float2*>(base + (r + 8) * XROWW + 8);
                ss[s][0] += (v00.x + v00.y) + (v01.x + v01.y);
                ss[s][1] += (v10.x + v10.y) + (v11.x + v11.y);
                sq[s][0] += v00.x * v00.x + v00.y * v00.y + v01.x * v01.x + v01.y * v01.y;
                sq[s][1] += v10.x * v10.x + v10.y * v10.y + v11.x * v11.x + v11.y * v11.y;
                a[s][0] = pack_h2(v00.x, v00.y);
                a[s][1] = pack_h2(v10.x, v10.y);
                a[s][2] = pack_h2(v01.x, v01.y);
                a[s][3] = pack_h2(v11.x, v11.y);
            }
            #pragma unroll
            for (int j = 0; j < NFRAG; j++) {
                mma_f16(acc[0][j], a[0], b[j]);
                mma_f16(acc[1][j], a[1], b[j]);
            }
        }
    }

    // Finalize stats: sum over tig (lanes sharing grp)
    float rs_[2][2], nmu[2][2];
    #pragma unroll
    for (int s = 0; s < 2; s++)
        #pragma unroll
        for (int h = 0; h < 2; h++) {
            float t1 = ss[s][h], t2 = sq[s][h];
            #pragma unroll
            for (int off = 1; off < 4; off <<= 1) {
                t1 += __shfl_xor_sync(0xffffffffu, t1, off);
                t2 += __shfl_xor_sync(0xffffffffu, t2, off);
            }
            float m   = t1 * (1.0f / D_DIM);
            float var = fmaxf(t2 * (1.0f / D_DIM) - m * m, 0.0f);
            float r   = rsqrtf(var + 1e-6f);
            rs_[s][h] = r;
            nmu[s][h] = -m * r;
        }

    // Epilogue: out = rs*acc + (-rs*mu*S' + cb)
    #pragma unroll
    for (int s = 0; s < 2; s++) {
        const float r0 = rs_[s][0], u0 = nmu[s][0];
        const float r1 = rs_[s][1], u1 = nmu[s][1];
        #pragma unroll
        for (int j = 0; j < NFRAG; j++) {
            int n = (nf0 + j) * 8 + 2 * tig;
            if (n < OUT_DIM) {
                float sp0 = smem[SP_OFF + n], sp1 = smem[SP_OFF + n + 1];
                float cb0 = smem[CB_OFF + n], cb1 = smem[CB_OFF + n + 1];
                long long row0 = R0 + mrow + s * 16;
                float2 v0 = make_float2(fmaf(r0, acc[s][j][0], fmaf(u0, sp0, cb0)),
                                        fmaf(r0, acc[s][j][1], fmaf(u0, sp1, cb1)));
                float2 v1 = make_float2(fmaf(r1, acc[s][j][2], fmaf(u1, sp0, cb0)),
                                        fmaf(r1, acc[s][j][3], fmaf(u1, sp1, cb1)));
                *reinterpret_cast<float2*>(out + row0 * OUT_DIM + n)       = v0;
                *reinterpret_cast<float2*>(out + (row0 + 8) * OUT_DIM + n) = v1;
            }
        }
    }
}

extern "C" void kernel_launch(void* const* d_in, const int* in_sizes, int n_in,
                              void* d_out, int out_size) {
    const float* x     = (const float*)d_in[0];
    const float* gamma = (const float*)d_in[1];
    const float* beta  = (const float*)d_in[2];
    const float* W     = (const float*)d_in[3];
    const float* b     = (const float*)d_in[4];
    float* out = (float*)d_out;

    cudaFuncSetAttribute(ln_gemm_kernel,
                         cudaFuncAttributeMaxDynamicSharedMemorySize, SMEM_BYTES);

    const int rows = in_sizes[0] / D_DIM;   // 65536
    prep_kernel<<<NPAD, D_DIM>>>(W, gamma, beta, b);
    ln_gemm_kernel<<<rows / TM, 256, SMEM_BYTES>>>(x, out);
}

// round 17
// speedup vs baseline: 3.0573x; 1.1575x over previous
#include <cuda_runtime.h>
#include <cuda_fp16.h>
#include <cstdint>

#define D_DIM 768
#define OUT_DIM 196
#define NPAD 208
#define TM 128
#define NH 104                         // N columns per CTA
#define BK 32
#define NTILES 24
#define NFRAG 13

#define XROWW 40                       // x row stride (words)
#define XW (TM * XROWW)                // 5120 words / stage
#define WROWW 24                       // W words per n per k-tile (16 data + 8 pad)
#define WW (NH * WROWW)                // 2496 words / stage
#define XSTAGES 4
#define WSTAGES 2

#define X_OFF 0
#define W_OFF (XSTAGES * XW)           // 20480
#define SP_OFF (W_OFF + WSTAGES * WW)  // 25472
#define CB_OFF (SP_OFF + NH)
#define SMEM_WORDS (CB_OFF + NH)       // 25680
#define SMEM_BYTES (SMEM_WORDS * 4)    // 102720 -> 2 CTAs/SM

__device__ __half g_wph[NTILES * NPAD * 32];  // fp16 gamma*W, frag-packed per k-tile
__device__ float  g_sp[NPAD];                 // row sums of fp16-rounded gamma*W
__device__ float  g_cb[NPAD];                 // beta.W + bias

__device__ __forceinline__ uint32_t pack_h2(float lo, float hi) {
    uint32_t u;
    asm("cvt.rn.f16x2.f32 %0, %1, %2;" : "=r"(u) : "f"(hi), "f"(lo));
    return u;
}
__device__ __forceinline__ void mma_f16(float* c, const uint32_t* a, const uint32_t* b) {
    asm volatile(
        "mma.sync.aligned.m16n8k16.row.col.f32.f16.f16.f32 "
        "{%0,%1,%2,%3}, {%4,%5,%6,%7}, {%8,%9}, {%0,%1,%2,%3};"
        : "+f"(c[0]), "+f"(c[1]), "+f"(c[2]), "+f"(c[3])
        : "r"(a[0]), "r"(a[1]), "r"(a[2]), "r"(a[3]), "r"(b[0]), "r"(b[1]));
}
__device__ __forceinline__ void cp16(void* dst, const void* src) {
    uint32_t d = (uint32_t)__cvta_generic_to_shared(dst);
    asm volatile("cp.async.cg.shared.global [%0], [%1], 16;" :: "r"(d), "l"(src));
}

// ---------------- Prologue: fold gamma into W (fp16), frag-pack, precompute sums ----------------
__global__ void prep_kernel(const float* __restrict__ W,
                            const float* __restrict__ gamma,
                            const float* __restrict__ beta,
                            const float* __restrict__ bias)
{
    __shared__ float rs_[24], rc_[24];
    const int n = blockIdx.x;           // 0..207
    const int k = threadIdx.x;          // 0..767
    const int lane = k & 31, wid = k >> 5;

    float wg = 0.f, cb = 0.f;
    if (n < OUT_DIM) {
        float w = W[n * D_DIM + k];
        wg = w * gamma[k];
        cb = beta[k] * w;
    }
    __half wph = __float2half_rn(wg);
    // frag-packed: k-tile kt, chunk c = (k%32)/16, j = k%16
    {
        int kt = k >> 5, kk = k & 31;
        int c  = kk >> 4, j = kk & 15;
        int word = ((j & 7) >> 1) * 2 + (j >> 3);
        g_wph[(kt * NPAD + n) * 32 + (c * 8 + word) * 2 + (j & 1)] = wph;
    }

    float s1 = __half2float(wph);
    #pragma unroll
    for (int off = 16; off; off >>= 1) {
        s1 += __shfl_xor_sync(0xffffffffu, s1, off);
        cb += __shfl_xor_sync(0xffffffffu, cb, off);
    }
    if (lane == 0) { rs_[wid] = s1; rc_[wid] = cb; }
    __syncthreads();
    if (k < 32) {
        float a = (k < 24) ? rs_[k] : 0.f;
        float c = (k < 24) ? rc_[k] : 0.f;
        #pragma unroll
        for (int off = 16; off; off >>= 1) {
            a += __shfl_xor_sync(0xffffffffu, a, off);
            c += __shfl_xor_sync(0xffffffffu, c, off);
        }
        if (k == 0) {
            g_sp[n] = a;
            g_cb[n] = (n < OUT_DIM) ? (c + bias[n]) : 0.f;
        }
    }
}

// ---------------- Main: N-split CTAs (2/SM), 8 warps x 16-row tiles, register stats ----------------
__global__ __launch_bounds__(256, 2)
void ln_gemm_kernel(const float* __restrict__ x, float* __restrict__ out)
{
    extern __shared__ float smem[];
    const int tid  = threadIdx.x;
    const int lane = tid & 31;
    const int wrp  = tid >> 5;                 // 0..7 : M-warp (16 rows each)
    const int rowblk = blockIdx.x >> 1;
    const int nh     = blockIdx.x & 1;         // N half
    const long long R0 = (long long)rowblk * TM;

    const int grp = lane >> 2;
    const int tig = lane & 3;
    const int mrow = wrp * 16 + grp;           // rows mrow, mrow+8

    if (tid < NH) {
        smem[SP_OFF + tid] = g_sp[nh * NH + tid];
        smem[CB_OFF + tid] = g_cb[nh * NH + tid];
    }

    const float* xg = x + R0 * D_DIM;
    const __half* wg = g_wph + nh * NH * 32;

    auto fill_x = [&](int tile, int stage) {
        float* xd = smem + X_OFF + stage * XW;
        const float* src = xg + tile * BK;
        #pragma unroll
        for (int i = 0; i < 4; i++) {
            int idx = tid + i * 256;           // 1024 16B chunks
            int r = idx >> 3, c = idx & 7;
            cp16(xd + r * XROWW + c * 4, src + r * D_DIM + c * 4);
        }
    };
    auto fill_w = [&](int tile, int stage) {
        float* wd = smem + W_OFF + stage * WW;
        const __half* src = wg + (long long)tile * NPAD * 32;
        #pragma unroll
        for (int i = 0; i < 2; i++) {
            int idx = tid + i * 256;           // 416 16B chunks
            if (idx < NH * 4) {
                int r = idx >> 2, c = idx & 3;
                cp16(wd + r * WROWW + c * 4, src + r * 32 + c * 8);
            }
        }
    };

    // Prologue: G1={x0,W0}, G2={x1,W1}, G3={x2}
    fill_x(0, 0); fill_w(0, 0);
    asm volatile("cp.async.commit_group;");
    fill_x(1, 1); fill_w(1, 1);
    asm volatile("cp.async.commit_group;");
    fill_x(2, 2);
    asm volatile("cp.async.commit_group;");

    float acc[NFRAG][4];
    #pragma unroll
    for (int j = 0; j < NFRAG; j++)
        #pragma unroll
        for (int q = 0; q < 4; q++) acc[j][q] = 0.f;

    // register stats: h=0 row mrow, h=1 row mrow+8 (each (row,col) once per warp)
    float ss[2] = {0.f, 0.f};
    float sq[2] = {0.f, 0.f};

    for (int kt = 0; kt < NTILES; kt++) {
        const int st4 = kt & 3;
        const int st2 = kt & 1;

        asm volatile("cp.async.wait_group 1;");
        __syncthreads();

        // refills: W tile kt+1 -> stage (kt+1)&1 ; x tile kt+3 -> stage (kt+3)&3
        if (kt >= 1 && kt + 1 < NTILES) fill_w(kt + 1, (kt + 1) & 1);
        asm volatile("cp.async.commit_group;");        // Gw
        if (kt + 3 < NTILES) fill_x(kt + 3, (kt + 3) & 3);
        asm volatile("cp.async.commit_group;");        // Gx (newest)

        const float* xs = smem + X_OFF + st4 * XW;
        const uint32_t* ws = reinterpret_cast<const uint32_t*>(smem + W_OFF + st2 * WW);

        #pragma unroll
        for (int c = 0; c < 2; c++) {          // two k16 chunks
            // A frags: fp32 pairs -> stats -> f16x2
            const float* base = xs + c * 16 + tig * 2;
            float2 v00 = *reinterpret_cast<const float2*>(base + mrow * XROWW);
            float2 v10 = *reinterpret_cast<const float2*>(base + (mrow + 8) * XROWW);
            float2 v01 = *reinterpret_cast<const float2*>(base + mrow * XROWW + 8);
            float2 v11 = *reinterpret_cast<const float2*>(base + (mrow + 8) * XROWW + 8);
            ss[0] += (v00.x + v00.y) + (v01.x + v01.y);
            ss[1] += (v10.x + v10.y) + (v11.x + v11.y);
            sq[0] += v00.x * v00.x + v00.y * v00.y + v01.x * v01.x + v01.y * v01.y;
            sq[1] += v10.x * v10.x + v10.y * v10.y + v11.x * v11.x + v11.y * v11.y;
            uint32_t a[4];
            a[0] = pack_h2(v00.x, v00.y);
            a[1] = pack_h2(v10.x, v10.y);
            a[2] = pack_h2(v01.x, v01.y);
            a[3] = pack_h2(v11.x, v11.y);

            #pragma unroll
            for (int j = 0; j < NFRAG; j++) {
                const int nb = j * 8 + grp;
                uint2 bv = *reinterpret_cast<const uint2*>(ws + nb * WROWW + c * 8 + tig * 2);
                uint32_t b[2] = { bv.x, bv.y };
                mma_f16(acc[j], a, b);
            }
        }
    }

    // Finalize stats: reduce over tig (lane bits 0,1)
    float rs_[2], nmu[2];
    #pragma unroll
    for (int h = 0; h < 2; h++) {
        float t1 = ss[h], t2 = sq[h];
        #pragma unroll
        for (int off = 1; off < 4; off <<= 1) {
            t1 += __shfl_xor_sync(0xffffffffu, t1, off);
            t2 += __shfl_xor_sync(0xffffffffu, t2, off);
        }
        float m   = t1 * (1.0f / D_DIM);
        float var = fmaxf(t2 * (1.0f / D_DIM) - m * m, 0.0f);
        float r   = rsqrtf(var + 1e-6f);
        rs_[h] = r;
        nmu[h] = -m * r;
    }

    // Epilogue: out = rs*acc + (-rs*mu*S' + cb)
    {
        const float r0 = rs_[0], u0 = nmu[0];
        const float r1 = rs_[1], u1 = nmu[1];
        #pragma unroll
        for (int j = 0; j < NFRAG; j++) {
            int nl = j * 8 + 2 * tig;
            int ng = nh * NH + nl;
            if (ng < OUT_DIM) {
                float sp0 = smem[SP_OFF + nl], sp1 = smem[SP_OFF + nl + 1];
                float cb0 = smem[CB_OFF + nl], cb1 = smem[CB_OFF + nl + 1];
                long long row0 = R0 + mrow;
                float2 v0 = make_float2(fmaf(r0, acc[j][0], fmaf(u0, sp0, cb0)),
                                        fmaf(r0, acc[j][1], fmaf(u0, sp1, cb1)));
                float2 v1 = make_float2(fmaf(r1, acc[j][2], fmaf(u1, sp0, cb0)),
                                        fmaf(r1, acc[j][3], fmaf(u1, sp1, cb1)));
                *reinterpret_cast<float2*>(out + row0 * OUT_DIM + ng)       = v0;
                *reinterpret_cast<float2*>(out + (row0 + 8) * OUT_DIM + ng) = v1;
            }
        }
    }
}

extern "C" void kernel_launch(void* const* d_in, const int* in_sizes, int n_in,
                              void* d_out, int out_size) {
    const float* x     = (const float*)d_in[0];
    const float* gamma = (const float*)d_in[1];
    const float* beta  = (const float*)d_in[2];
    const float* W     = (const float*)d_in[3];
    const float* b     = (const float*)d_in[4];
    float* out = (float*)d_out;

    cudaFuncSetAttribute(ln_gemm_kernel,
                         cudaFuncAttributeMaxDynamicSharedMemorySize, SMEM_BYTES);

    const int rows = in_sizes[0] / D_DIM;   // 65536
    prep_kernel<<<NPAD, D_DIM>>>(W, gamma, beta, b);
    ln_gemm_kernel<<<(rows / TM) * 2, 256, SMEM_BYTES>>>(x, out);
}